// round 2
// baseline (speedup 1.0000x reference)
#include <cuda_runtime.h>

#define BATCH 8
#define MODES 16
#define NPH   8
#define NST   12870
#define OUTD  128
#define NSUB  256

// ---------------- device scratch (no allocation allowed) ----------------
__device__ __align__(16) float2 g_Uin[BATCH][MODES][NPH];        // 8 KB
__device__ __align__(16) float2 g_Plow [BATCH][NSUB][256];       // 4 MB  [b][s][c]
__device__ __align__(16) float2 g_Phigh[BATCH][NSUB][256];       // 4 MB  [b][s][c], sign folded
__device__ float g_praw[BATCH][NST];
__device__ float g_sum[BATCH];
__device__ float g_acc[BATCH * OUTD];

// ---------------- kernel 1: build Uin = B diag(e^{ix}) A, zero accumulators ----
__global__ void k_setup(const float* __restrict__ x,
                        const float* __restrict__ th1,
                        const float* __restrict__ th2,
                        const float* __restrict__ mr,
                        const float* __restrict__ mi) {
    __shared__ float2 e1[16], e2[16], ex[BATCH][16];
    __shared__ float2 A[16][16], Bm[16][16];
    int t = threadIdx.x;
    if (t < 16) {
        float s, c;
        sincosf(th1[t], &s, &c); e1[t] = make_float2(c, s);
        sincosf(th2[t], &s, &c); e2[t] = make_float2(c, s);
    }
    if (t < BATCH * 16) {
        int b = t >> 4, m = t & 15;
        float s, c; sincosf(x[b * 16 + m], &s, &c);
        ex[b][m] = make_float2(c, s);
    }
    __syncthreads();
    {
        int i = t >> 4, j = t & 15;
        float ar = 0, ai = 0, br = 0, bi = 0;
        for (int m = 0; m < 16; m++) {
            // A[i][j] = sum_m M1[i][m] * e1[m] * M0[m][j]
            float m1r = mr[256 + i * 16 + m], m1i = mi[256 + i * 16 + m];
            float m0r = mr[m * 16 + j],       m0i = mi[m * 16 + j];
            float tr = e1[m].x * m0r - e1[m].y * m0i;
            float ti = e1[m].x * m0i + e1[m].y * m0r;
            ar += m1r * tr - m1i * ti;
            ai += m1r * ti + m1i * tr;
            // B[i][j] = sum_m M3[i][m] * e2[m] * M2[m][j]
            float m3r = mr[3 * 256 + i * 16 + m], m3i = mi[3 * 256 + i * 16 + m];
            float m2r = mr[2 * 256 + m * 16 + j], m2i = mi[2 * 256 + m * 16 + j];
            float ur = e2[m].x * m2r - e2[m].y * m2i;
            float ui = e2[m].x * m2i + e2[m].y * m2r;
            br += m3r * ur - m3i * ui;
            bi += m3r * ui + m3i * ur;
        }
        A[i][j]  = make_float2(ar, ai);
        Bm[i][j] = make_float2(br, bi);
    }
    __syncthreads();
    // Uin[b][p][n] = sum_m Bm[p][m] * ex[b][m] * A[m][n]   (n < 8 only)
    for (int q = 0; q < 4; q++) {
        int idx = t + q * 256;           // b*128 + p*8 + n
        int b = idx >> 7, p = (idx >> 3) & 15, n = idx & 7;
        float ur = 0, ui = 0;
        for (int m = 0; m < 16; m++) {
            float tr = ex[b][m].x * A[m][n].x - ex[b][m].y * A[m][n].y;
            float ti = ex[b][m].x * A[m][n].y + ex[b][m].y * A[m][n].x;
            ur += Bm[p][m].x * tr - Bm[p][m].y * ti;
            ui += Bm[p][m].x * ti + Bm[p][m].y * tr;
        }
        g_Uin[b][p][n] = make_float2(ur, ui);
    }
    if (t < BATCH) g_sum[t] = 0.f;
    for (int q = t; q < BATCH * OUTD; q += 256) g_acc[q] = 0.f;
}

// ---------------- kernel 2: build subset-product tables Plow / Phigh ----------
#define CS2 16
__global__ void k_tables() {
    // grid: x = s-chunk (16 chunks of 16 s), y = side (0 low / 1 high), z = batch
    int t = threadIdx.x;
    int s0 = blockIdx.x * CS2;
    int side = blockIdx.y, b = blockIdx.z;
    __shared__ float2 uin[8][8];
    __shared__ float2 vs[CS2][8];
    __shared__ float2 P[256][CS2 + 1];   // pad to dodge bank conflicts
    if (t < 64) {
        int r = t >> 3, n = t & 7;
        uin[r][n] = g_Uin[b][side * 8 + r][n];
    }
    __syncthreads();
    if (t < CS2 * 8) {
        int sl = t >> 3, r = t & 7, s = s0 + sl;
        float vr = 0, vi = 0;
        for (int n = 0; n < 8; n++)
            if ((s >> n) & 1) { vr += uin[r][n].x; vi += uin[r][n].y; }
        vs[sl][r] = make_float2(vr, vi);
    }
    if (t < CS2) P[0][t] = make_float2(1.f, 0.f);
    __syncthreads();
    // DP over rows: P[c | 1<<r] = P[c] * V[r]
    for (int r = 0; r < 8; r++) {
        int cnt = (1 << r) * CS2;
        for (int idx = t; idx < cnt; idx += 256) {
            int cprev = idx >> 4, sl = idx & 15;
            float2 p = P[cprev][sl], v = vs[sl][r];
            P[cprev | (1 << r)][sl] =
                make_float2(p.x * v.x - p.y * v.y, p.x * v.y + p.y * v.x);
        }
        __syncthreads();
    }
    // write [b][s][c]; fold Ryser sign (-1)^popc(s) into high table
    float2* dst = (side == 0) ? &g_Plow[b][0][0] : &g_Phigh[b][0][0];
    for (int idx = t; idx < 256 * CS2; idx += 256) {
        int c = idx & 255, sl = idx >> 8;
        int s = s0 + sl;
        float2 p = P[c][sl];
        if (side == 1 && (__popc(s) & 1)) { p.x = -p.x; p.y = -p.y; }
        dst[(size_t)s * 256 + c] = p;
    }
}

// ---------------- kernel 3: per-state Ryser dot: amp = sum_s Plow*Phigh -------
#define SPT  4
#define CS3  8
#define TPB3 256
__global__ void k_states(const int* __restrict__ rows_idx) {
    int t = threadIdx.x;
    int b = blockIdx.y;
    int kbase = blockIdx.x * (TPB3 * SPT);
    __shared__ __align__(16) float2 sh_lo[CS3][256];
    __shared__ __align__(16) float2 sh_hi[CS3][256];
    int cl[SPT], ch[SPT];
    float accR[SPT], accI[SPT];
    bool valid[SPT];
#pragma unroll
    for (int q = 0; q < SPT; q++) {
        int k = kbase + t + q * TPB3;
        valid[q] = (k < NST);
        cl[q] = 0; ch[q] = 0; accR[q] = 0.f; accI[q] = 0.f;
        if (valid[q]) {
            for (int j = 0; j < 8; j++) {
                int r = rows_idx[k * 8 + j];
                if (r < 8) cl[q] |= 1 << r; else ch[q] |= 1 << (r - 8);
            }
        }
    }
    const float2* lo = &g_Plow[b][0][0];
    const float2* hi = &g_Phigh[b][0][0];
    for (int s0 = 0; s0 < NSUB; s0 += CS3) {
        __syncthreads();
        const float4* lo4 = (const float4*)(lo + (size_t)s0 * 256);
        const float4* hi4 = (const float4*)(hi + (size_t)s0 * 256);
        float4* slo4 = (float4*)&sh_lo[0][0];
        float4* shi4 = (float4*)&sh_hi[0][0];
        for (int idx = t; idx < CS3 * 128; idx += TPB3) {
            slo4[idx] = lo4[idx];
            shi4[idx] = hi4[idx];
        }
        __syncthreads();
#pragma unroll
        for (int sl = 0; sl < CS3; sl++) {
#pragma unroll
            for (int q = 0; q < SPT; q++) {
                float2 L = sh_lo[sl][cl[q]];
                float2 H = sh_hi[sl][ch[q]];
                accR[q] += L.x * H.x - L.y * H.y;
                accI[q] += L.x * H.y + L.y * H.x;
            }
        }
    }
    float local = 0.f;
#pragma unroll
    for (int q = 0; q < SPT; q++) {
        if (valid[q]) {
            int k = kbase + t + q * TPB3;
            float p = accR[q] * accR[q] + accI[q] * accI[q];
            g_praw[b][k] = p;
            local += p;
        }
    }
    for (int off = 16; off; off >>= 1)
        local += __shfl_down_sync(0xffffffffu, local, off);
    if ((t & 31) == 0) atomicAdd(&g_sum[b], local);
}

// ---------------- kernel 4: acc = praw @ weight (unnormalized) ----------------
#define KT4  128
#define KSZ4 101   // ceil(12870/128)
__global__ void k_gemm(const float* __restrict__ weight) {
    int t = threadIdx.x;
    int n = t & 127;
    int g = t >> 7;                    // 0..1
    int klo = blockIdx.x * KSZ4;
    int ksz = NST - klo; if (ksz > KSZ4) ksz = KSZ4;
    if (ksz <= 0) return;
    __shared__ float pr[BATCH][KSZ4 + 3];
    for (int idx = t; idx < BATCH * ksz; idx += 256) {
        int bb = idx / ksz, kk = idx - bb * ksz;
        pr[bb][kk] = g_praw[bb][klo + kk];
    }
    __syncthreads();
    float acc[BATCH];
#pragma unroll
    for (int bb = 0; bb < BATCH; bb++) acc[bb] = 0.f;
    for (int kk = g; kk < ksz; kk += 2) {
        float w = weight[(size_t)(klo + kk) * OUTD + n];
#pragma unroll
        for (int bb = 0; bb < BATCH; bb++) acc[bb] += w * pr[bb][kk];
    }
#pragma unroll
    for (int bb = 0; bb < BATCH; bb++)
        atomicAdd(&g_acc[bb * OUTD + n], acc[bb]);
}

// ---------------- kernel 5: normalize + bias ----------------------------------
__global__ void k_final(const float* __restrict__ bias, float* __restrict__ out) {
    int t = blockIdx.x * 256 + threadIdx.x;
    if (t < BATCH * OUTD) {
        int b = t >> 7, n = t & 127;
        out[t] = g_acc[t] / g_sum[b] + bias[n];
    }
}

// ---------------- launch -------------------------------------------------------
extern "C" void kernel_launch(void* const* d_in, const int* in_sizes, int n_in,
                              void* d_out, int out_size) {
    const float* x   = (const float*)d_in[0];
    const float* th1 = (const float*)d_in[1];
    const float* th2 = (const float*)d_in[2];
    const float* mr  = (const float*)d_in[3];
    const float* mi  = (const float*)d_in[4];
    const float* w   = (const float*)d_in[5];
    const float* bia = (const float*)d_in[6];
    const int* rows  = (const int*)d_in[7];
    float* out = (float*)d_out;

    k_setup<<<1, 256>>>(x, th1, th2, mr, mi);
    k_tables<<<dim3(NSUB / CS2, 2, BATCH), 256>>>();
    int blocks_k = (NST + TPB3 * SPT - 1) / (TPB3 * SPT);   // 13
    k_states<<<dim3(blocks_k, BATCH), TPB3>>>(rows);
    k_gemm<<<KT4, 256>>>(w);
    k_final<<<4, 256>>>(bia, out);
}

// round 3
// speedup vs baseline: 2.1028x; 2.1028x over previous
#include <cuda_runtime.h>

#define BATCH 8
#define MODES 16
#define NPH   8
#define NST   12870
#define OUTD  128
#define NSUB  256
#define KQN   8      // K-split count for class GEMMs
#define KSL   (NSUB / KQN)   // 32 s per class block
#define KC    16     // shared stage depth

// class sizes C(8,j), column offsets, output-slot offsets
__constant__ int c_NJ[9]   = {1, 8, 28, 56, 70, 56, 28, 8, 1};
__constant__ int c_OFFJ[9] = {0, 1, 9, 37, 93, 163, 219, 247, 255};
__constant__ int c_OFF2[9] = {0, 1, 65, 849, 3985, 8885, 12021, 12805, 12869};

// ---------------- device scratch ----------------
__device__ __align__(16) float2 g_Uin[BATCH][MODES][NPH];
__device__ __align__(16) float2 g_PS[BATCH][2][NSUB][256];   // class-sorted cols, 8MB
__device__ int    g_clsval[256];          // byte value at sorted position a
__device__ int    g_invmap[NST];          // (j,a,b) slot -> state k
__device__ __align__(16) float2 g_part[KQN][BATCH][NST];     // 6.6MB partial amps
__device__ float  g_praw[BATCH][NST];
__device__ float  g_sum[BATCH];
__device__ float  g_acc[BATCH * OUTD];

// ---------------- kernel 1: Uin = B diag(e^{ix}) A, zero accumulators ----
__global__ void k_setup(const float* __restrict__ x,
                        const float* __restrict__ th1,
                        const float* __restrict__ th2,
                        const float* __restrict__ mr,
                        const float* __restrict__ mi) {
    __shared__ float2 e1[16], e2[16], ex[BATCH][16];
    __shared__ float2 A[16][16], Bm[16][16];
    int t = threadIdx.x;
    if (t < 16) {
        float s, c;
        sincosf(th1[t], &s, &c); e1[t] = make_float2(c, s);
        sincosf(th2[t], &s, &c); e2[t] = make_float2(c, s);
    }
    if (t < BATCH * 16) {
        int b = t >> 4, m = t & 15;
        float s, c; sincosf(x[b * 16 + m], &s, &c);
        ex[b][m] = make_float2(c, s);
    }
    __syncthreads();
    {
        int i = t >> 4, j = t & 15;
        float ar = 0, ai = 0, br = 0, bi = 0;
        for (int m = 0; m < 16; m++) {
            float m1r = mr[256 + i * 16 + m], m1i = mi[256 + i * 16 + m];
            float m0r = mr[m * 16 + j],       m0i = mi[m * 16 + j];
            float tr = e1[m].x * m0r - e1[m].y * m0i;
            float ti = e1[m].x * m0i + e1[m].y * m0r;
            ar += m1r * tr - m1i * ti;
            ai += m1r * ti + m1i * tr;
            float m3r = mr[3 * 256 + i * 16 + m], m3i = mi[3 * 256 + i * 16 + m];
            float m2r = mr[2 * 256 + m * 16 + j], m2i = mi[2 * 256 + m * 16 + j];
            float ur = e2[m].x * m2r - e2[m].y * m2i;
            float ui = e2[m].x * m2i + e2[m].y * m2r;
            br += m3r * ur - m3i * ui;
            bi += m3r * ui + m3i * ur;
        }
        A[i][j]  = make_float2(ar, ai);
        Bm[i][j] = make_float2(br, bi);
    }
    __syncthreads();
    for (int q = 0; q < 4; q++) {
        int idx = t + q * 256;           // b*128 + p*8 + n
        int b = idx >> 7, p = (idx >> 3) & 15, n = idx & 7;
        float ur = 0, ui = 0;
        for (int m = 0; m < 16; m++) {
            float tr = ex[b][m].x * A[m][n].x - ex[b][m].y * A[m][n].y;
            float ti = ex[b][m].x * A[m][n].y + ex[b][m].y * A[m][n].x;
            ur += Bm[p][m].x * tr - Bm[p][m].y * ti;
            ui += Bm[p][m].x * ti + Bm[p][m].y * tr;
        }
        g_Uin[b][p][n] = make_float2(ur, ui);
    }
    if (t < BATCH) g_sum[t] = 0.f;
    for (int q = t; q < BATCH * OUTD; q += 256) g_acc[q] = 0.f;
}

// ---------------- kernel 2: class permutation + inverse state map ----------
__global__ void k_map(const int* __restrict__ rows) {
    __shared__ int s_rank[256];
    int c = threadIdx.x;
    int pc = __popc(c);
    int r = 0;
    for (int cp = 0; cp < c; cp++) r += (__popc(cp) == pc) ? 1 : 0;
    s_rank[c] = r;
    g_clsval[c_OFFJ[pc] + r] = c;
    __syncthreads();
    for (int k = threadIdx.x; k < NST; k += 256) {
        int cl = 0, ch = 0;
        for (int j = 0; j < 8; j++) {
            int rr = rows[k * 8 + j];
            if (rr < 8) cl |= 1 << rr; else ch |= 1 << (rr - 8);
        }
        int j = __popc(cl);
        int a = s_rank[cl], b = s_rank[ch];
        g_invmap[c_OFF2[j] + a * c_NJ[j] + b] = k;
    }
}

// ---------------- kernel 3: subset-product tables, class-sorted cols -------
#define CS2 16
__global__ void k_tables() {
    int t = threadIdx.x;
    int s0 = blockIdx.x * CS2;
    int side = blockIdx.y, b = blockIdx.z;
    __shared__ float2 uin[8][8];
    __shared__ float2 vs[CS2][8];
    __shared__ float2 P[256][CS2 + 1];
    __shared__ int cv[256];
    if (t < 64) {
        int r = t >> 3, n = t & 7;
        uin[r][n] = g_Uin[b][side * 8 + r][n];
    }
    cv[t] = g_clsval[t];
    __syncthreads();
    if (t < CS2 * 8) {
        int sl = t >> 3, r = t & 7, s = s0 + sl;
        float vr = 0, vi = 0;
        for (int n = 0; n < 8; n++)
            if ((s >> n) & 1) { vr += uin[r][n].x; vi += uin[r][n].y; }
        vs[sl][r] = make_float2(vr, vi);
    }
    if (t < CS2) P[0][t] = make_float2(1.f, 0.f);
    __syncthreads();
    for (int r = 0; r < 8; r++) {
        int cnt = (1 << r) * CS2;
        for (int idx = t; idx < cnt; idx += 256) {
            int cprev = idx >> 4, sl = idx & 15;
            float2 p = P[cprev][sl], v = vs[sl][r];
            P[cprev | (1 << r)][sl] =
                make_float2(p.x * v.x - p.y * v.y, p.x * v.y + p.y * v.x);
        }
        __syncthreads();
    }
    // coalesced write in class-sorted order; Ryser sign folded into high side
    for (int idx = t; idx < 256 * CS2; idx += 256) {
        int a = idx & 255, sl = idx >> 8;
        int c = cv[a];
        int s = s0 + sl;
        float2 p = P[c][sl];
        if (side == 1 && (__popc(s) & 1)) { p.x = -p.x; p.y = -p.y; }
        g_PS[b][side][s][a] = p;
    }
}

// ---------------- kernel 4: per-class dense complex GEMMs ------------------
template<int NI>
__device__ __forceinline__ void class_gemm(float2 (*shL)[KC][81], int b, int j, int kq) {
    const int n    = c_NJ[j];
    const int offL = c_OFFJ[j];
    const int offH = c_OFFJ[8 - j];
    const int off2 = c_OFF2[j];
    const int ty = threadIdx.x >> 4, tx = threadIdx.x & 15;
    const int W = NI * 16;

    float2 acc[NI][NI];
#pragma unroll
    for (int i = 0; i < NI; i++)
#pragma unroll
        for (int i2 = 0; i2 < NI; i2++) acc[i][i2] = make_float2(0.f, 0.f);

    const float2* Lg = &g_PS[b][0][0][0];
    const float2* Hg = &g_PS[b][1][0][0];
    const int s0 = kq * KSL;

    for (int st = 0; st < KSL; st += KC) {
        __syncthreads();
        for (int idx = threadIdx.x; idx < KC * W; idx += 256) {
            int kk = idx / W, a = idx - kk * W;
            int srow = (s0 + st + kk) * 256;
            float2 lv = (a < n) ? Lg[srow + offL + a] : make_float2(0.f, 0.f);
            float2 hv = (a < n) ? Hg[srow + offH + a] : make_float2(0.f, 0.f);
            shL[0][kk][a] = lv;
            shL[1][kk][a] = hv;
        }
        __syncthreads();
#pragma unroll 4
        for (int kk = 0; kk < KC; kk++) {
            float2 L[NI], H[NI];
#pragma unroll
            for (int i = 0; i < NI; i++) {
                L[i] = shL[0][kk][ty + 16 * i];
                H[i] = shL[1][kk][tx + 16 * i];
            }
#pragma unroll
            for (int i = 0; i < NI; i++)
#pragma unroll
                for (int i2 = 0; i2 < NI; i2++) {
                    acc[i][i2].x += L[i].x * H[i2].x - L[i].y * H[i2].y;
                    acc[i][i2].y += L[i].x * H[i2].y + L[i].y * H[i2].x;
                }
        }
    }
    float2* P = &g_part[kq][b][0];
#pragma unroll
    for (int i = 0; i < NI; i++) {
        int a = ty + 16 * i;
        if (a < n) {
#pragma unroll
            for (int i2 = 0; i2 < NI; i2++) {
                int bb = tx + 16 * i2;
                if (bb < n) P[off2 + a * n + bb] = acc[i][i2];
            }
        }
    }
}

__global__ __launch_bounds__(256) void k_classes() {
    __shared__ float2 sh[2][KC][81];
    int kq = blockIdx.x, j = blockIdx.y, b = blockIdx.z;
    int ni = (c_NJ[j] + 15) >> 4;
    switch (ni) {
        case 1: class_gemm<1>(sh, b, j, kq); break;
        case 2: class_gemm<2>(sh, b, j, kq); break;
        case 4: class_gemm<4>(sh, b, j, kq); break;
        default: class_gemm<5>(sh, b, j, kq); break;
    }
}

// ---------------- kernel 5: combine partials, square, scatter, sums --------
__global__ void k_reduce() {
    int slot = blockIdx.x * 256 + threadIdx.x;
    int b = blockIdx.y;
    float p = 0.f;
    if (slot < NST) {
        float sr = 0.f, si = 0.f;
#pragma unroll
        for (int kq = 0; kq < KQN; kq++) {
            float2 v = g_part[kq][b][slot];
            sr += v.x; si += v.y;
        }
        p = sr * sr + si * si;
        g_praw[b][g_invmap[slot]] = p;
    }
    for (int off = 16; off; off >>= 1)
        p += __shfl_down_sync(0xffffffffu, p, off);
    if ((threadIdx.x & 31) == 0 && p != 0.f) atomicAdd(&g_sum[b], p);
}

// ---------------- kernel 6: acc += praw @ weight ---------------------------
#define KCH 128
__global__ void k_gemm(const float* __restrict__ weight) {
    int t = threadIdx.x;
    int nl = t & 31;
    int kp = t >> 5;                      // 0..7
    int nq = blockIdx.y;
    int n = nq * 32 + nl;
    int k0 = blockIdx.x * KCH;
    int klen = NST - k0; if (klen > KCH) klen = KCH;

    __shared__ float pr[BATCH][KCH];
    for (int idx = t; idx < BATCH * KCH; idx += 256) {
        int bb = idx >> 7, kk = idx & 127;
        pr[bb][kk] = (kk < klen) ? g_praw[bb][k0 + kk] : 0.f;
    }
    __syncthreads();

    float acc[BATCH];
#pragma unroll
    for (int bb = 0; bb < BATCH; bb++) acc[bb] = 0.f;
    for (int kk = kp; kk < klen; kk += 8) {
        float wv = weight[(size_t)(k0 + kk) * OUTD + n];
#pragma unroll
        for (int bb = 0; bb < BATCH; bb++) acc[bb] += wv * pr[bb][kk];
    }
    __syncthreads();
    __shared__ float red[8][BATCH][32];
#pragma unroll
    for (int bb = 0; bb < BATCH; bb++) red[kp][bb][nl] = acc[bb];
    __syncthreads();
    {
        int bb = t >> 5;                  // 0..7
        float v = 0.f;
#pragma unroll
        for (int q = 0; q < 8; q++) v += red[q][bb][nl];
        atomicAdd(&g_acc[bb * OUTD + n], v);
    }
}

// ---------------- kernel 7: normalize + bias -------------------------------
__global__ void k_final(const float* __restrict__ bias, float* __restrict__ out) {
    int t = blockIdx.x * 256 + threadIdx.x;
    if (t < BATCH * OUTD) {
        int b = t >> 7, n = t & 127;
        out[t] = g_acc[t] / g_sum[b] + bias[n];
    }
}

// ---------------- launch ---------------------------------------------------
extern "C" void kernel_launch(void* const* d_in, const int* in_sizes, int n_in,
                              void* d_out, int out_size) {
    const float* x   = (const float*)d_in[0];
    const float* th1 = (const float*)d_in[1];
    const float* th2 = (const float*)d_in[2];
    const float* mr  = (const float*)d_in[3];
    const float* mi  = (const float*)d_in[4];
    const float* w   = (const float*)d_in[5];
    const float* bia = (const float*)d_in[6];
    const int* rows  = (const int*)d_in[7];
    float* out = (float*)d_out;

    k_setup<<<1, 256>>>(x, th1, th2, mr, mi);
    k_map<<<1, 256>>>(rows);
    k_tables<<<dim3(NSUB / CS2, 2, BATCH), 256>>>();
    k_classes<<<dim3(KQN, 9, BATCH), 256>>>();
    k_reduce<<<dim3((NST + 255) / 256, BATCH), 256>>>();
    k_gemm<<<dim3((NST + KCH - 1) / KCH, OUTD / 32), 256>>>(w);
    k_final<<<4, 256>>>(bia, out);
}

// round 4
// speedup vs baseline: 3.4579x; 1.6444x over previous
#include <cuda_runtime.h>

#define BATCH 8
#define MODES 16
#define NPH   8
#define NST   12870
#define OUTD  128
#define NDEL  128          // Glynn: 2^(n-1) terms
#define CS2   16           // delta-chunk in table kernel
#define KC    16           // K stage depth in class GEMM
#define NTILE 23

__constant__ int c_NJ[9]   = {1, 8, 28, 56, 70, 56, 28, 8, 1};
__constant__ int c_OFFJ[9] = {0, 1, 9, 37, 93, 163, 219, 247, 255};
__constant__ int c_OFF2[9] = {0, 1, 65, 849, 3985, 8885, 12021, 12805, 12869};
// tiles: {j, a0, b0} — all 32x32, uniform cost
__constant__ int c_TJ[NTILE]  = {4,4,4,4,4,4,4,4,4, 3,3,3,3, 5,5,5,5, 2,6,1,7,0,8};
__constant__ int c_TA[NTILE]  = {0,0,0,32,32,32,64,64,64, 0,0,32,32, 0,0,32,32, 0,0,0,0,0,0};
__constant__ int c_TB[NTILE]  = {0,32,64,0,32,64,0,32,64, 0,32,0,32, 0,32,0,32, 0,0,0,0,0,0};

// ---------------- device scratch ----------------
__device__ __align__(16) float2 g_PS[BATCH][2][NDEL][256];   // 4MB, class-sorted cols
__device__ int    g_invmap[NST];
__device__ float  g_praw[BATCH][NST];
__device__ float  g_sum[BATCH];
__device__ float  g_acc[BATCH * OUTD];

// ============ kernel 1: fused setup + class-map + Glynn tables ============
// grid: (NDEL/CS2=8, side=2, batch=8), 256 threads
__global__ __launch_bounds__(256) void k_tables(const float* __restrict__ x,
                                                const float* __restrict__ th1,
                                                const float* __restrict__ th2,
                                                const float* __restrict__ mr,
                                                const float* __restrict__ mi,
                                                const int* __restrict__ rows) {
    __shared__ float2 e1[16], e2[16], ex[16];
    __shared__ float2 A[16][16], Bm[16][16];
    __shared__ float2 uin[8][8];
    __shared__ float2 vs[CS2][8];
    __shared__ float2 P[256][CS2 + 1];
    __shared__ int cvs[256];      // sorted position -> mask
    __shared__ int s_rank[256];   // mask -> rank within its popc class

    int t = threadIdx.x;
    int d0 = blockIdx.x * CS2;
    int side = blockIdx.y, b = blockIdx.z;

    if (t < 16) {
        float s, c;
        sincosf(th1[t], &s, &c); e1[t] = make_float2(c, s);
        sincosf(th2[t], &s, &c); e2[t] = make_float2(c, s);
        sincosf(x[b * 16 + t], &s, &c); ex[t] = make_float2(c, s);
    }
    // rank table
    {
        int c = t, pc = __popc(c), r = 0;
        for (int cp = 0; cp < c; cp++) r += (__popc(cp) == pc) ? 1 : 0;
        s_rank[c] = r;
        cvs[c_OFFJ[pc] + r] = c;
    }
    __syncthreads();
    // A = M1 diag(e1) M0 ; B = M3 diag(e2) M2
    {
        int i = t >> 4, j = t & 15;
        float ar = 0, ai = 0, br = 0, bi = 0;
        for (int m = 0; m < 16; m++) {
            float m1r = mr[256 + i * 16 + m], m1i = mi[256 + i * 16 + m];
            float m0r = mr[m * 16 + j],       m0i = mi[m * 16 + j];
            float tr = e1[m].x * m0r - e1[m].y * m0i;
            float ti = e1[m].x * m0i + e1[m].y * m0r;
            ar += m1r * tr - m1i * ti;
            ai += m1r * ti + m1i * tr;
            float m3r = mr[3 * 256 + i * 16 + m], m3i = mi[3 * 256 + i * 16 + m];
            float m2r = mr[2 * 256 + m * 16 + j], m2i = mi[2 * 256 + m * 16 + j];
            float ur = e2[m].x * m2r - e2[m].y * m2i;
            float ui = e2[m].x * m2i + e2[m].y * m2r;
            br += m3r * ur - m3i * ui;
            bi += m3r * ui + m3i * ur;
        }
        A[i][j]  = make_float2(ar, ai);
        Bm[i][j] = make_float2(br, bi);
    }
    __syncthreads();
    // Uin rows for this side: p = side*8 + r, n < 8
    if (t < 64) {
        int r = t >> 3, n = t & 7, p = side * 8 + r;
        float ur = 0, ui = 0;
        for (int m = 0; m < 16; m++) {
            float tr = ex[m].x * A[m][n].x - ex[m].y * A[m][n].y;
            float ti = ex[m].x * A[m][n].y + ex[m].y * A[m][n].x;
            ur += Bm[p][m].x * tr - Bm[p][m].y * ti;
            ui += Bm[p][m].x * ti + Bm[p][m].y * tr;
        }
        uin[r][n] = make_float2(ur, ui);
    }
    __syncthreads();
    // Glynn row sums: V[r][d] = uin[r][0] + sum_{k=1..7} delta_k uin[r][k]
    if (t < CS2 * 8) {
        int sl = t >> 3, r = t & 7, d = d0 + sl;
        float vr = uin[r][0].x, vi = uin[r][0].y;
        for (int k = 1; k < 8; k++) {
            if ((d >> (k - 1)) & 1) { vr -= uin[r][k].x; vi -= uin[r][k].y; }
            else                    { vr += uin[r][k].x; vi += uin[r][k].y; }
        }
        vs[sl][r] = make_float2(vr, vi);
    }
    if (t < CS2) P[0][t] = make_float2(1.f, 0.f);
    __syncthreads();
    // subset-product DP
    for (int r = 0; r < 8; r++) {
        int cnt = (1 << r) * CS2;
        for (int idx = t; idx < cnt; idx += 256) {
            int cprev = idx >> 4, sl = idx & 15;
            float2 p = P[cprev][sl], v = vs[sl][r];
            P[cprev | (1 << r)][sl] =
                make_float2(p.x * v.x - p.y * v.y, p.x * v.y + p.y * v.x);
        }
        __syncthreads();
    }
    // write class-sorted; fold Glynn sign (prod delta = (-1)^popc(d)) + 2^-7 into high side
    for (int idx = t; idx < 256 * CS2; idx += 256) {
        int a = idx & 255, sl = idx >> 8;
        int d = d0 + sl;
        float2 p = P[cvs[a]][sl];
        if (side == 1) {
            float f = ((__popc(d) & 1) ? -0.0078125f : 0.0078125f);
            p.x *= f; p.y *= f;
        }
        g_PS[b][side][d][a] = p;
    }
    // inverse state map (side-0 blocks: 64 blocks x 256 threads = 16384 >= NST)
    if (side == 0) {
        int gid = (blockIdx.x + 8 * blockIdx.z) * 256 + t;
        if (gid < NST) {
            int cl = 0, ch = 0;
            for (int j = 0; j < 8; j++) {
                int rr = rows[gid * 8 + j];
                if (rr < 8) cl |= 1 << rr; else ch |= 1 << (rr - 8);
            }
            int j = __popc(cl);
            g_invmap[c_OFF2[j] + s_rank[cl] * c_NJ[j] + s_rank[ch]] = gid;
        }
    }
    // zero accumulators (one block)
    if (blockIdx.x == 0 && side == 0 && b == 0) {
        if (t < BATCH) g_sum[t] = 0.f;
        for (int q = t; q < BATCH * OUTD; q += 256) g_acc[q] = 0.f;
    }
}

// ============ kernel 2: uniform-tile class GEMMs + fused epilogue ============
// grid: (NTILE, BATCH), 256 threads; each block: 32x32 outputs x K=128
__global__ __launch_bounds__(256) void k_classes() {
    __shared__ __align__(16) float2 sh[2][KC][32];
    __shared__ float red[8];
    int t = threadIdx.x;
    int tile = blockIdx.x, b = blockIdx.y;
    int j  = c_TJ[tile];
    int a0 = c_TA[tile], b0 = c_TB[tile];
    int n  = c_NJ[j];
    int baseL = c_OFFJ[j] + a0;
    int baseH = c_OFFJ[8 - j] + b0;
    int limL = n - a0, limH = n - b0;
    int ty = t >> 4, tx = t & 15;

    float aR00 = 0, aI00 = 0, aR01 = 0, aI01 = 0;
    float aR10 = 0, aI10 = 0, aR11 = 0, aI11 = 0;

    const float2* Lg = &g_PS[b][0][0][0];
    const float2* Hg = &g_PS[b][1][0][0];

    for (int st = 0; st < NDEL; st += KC) {
        __syncthreads();
        for (int idx = t; idx < 2 * KC * 32; idx += 256) {
            int side = idx >> 9, rem = idx & 511;
            int kk = rem >> 5, c = rem & 31;
            const float2* src = side ? Hg : Lg;
            int lim = side ? limH : limL;
            int base = side ? baseH : baseL;
            float2 v = (c < lim) ? src[(size_t)(st + kk) * 256 + base + c]
                                 : make_float2(0.f, 0.f);
            sh[side][kk][c] = v;
        }
        __syncthreads();
#pragma unroll
        for (int kk = 0; kk < KC; kk++) {
            float2 L0 = sh[0][kk][ty], L1 = sh[0][kk][ty + 16];
            float2 H0 = sh[1][kk][tx], H1 = sh[1][kk][tx + 16];
            aR00 += L0.x * H0.x - L0.y * H0.y;  aI00 += L0.x * H0.y + L0.y * H0.x;
            aR01 += L0.x * H1.x - L0.y * H1.y;  aI01 += L0.x * H1.y + L0.y * H1.x;
            aR10 += L1.x * H0.x - L1.y * H0.y;  aI10 += L1.x * H0.y + L1.y * H0.x;
            aR11 += L1.x * H1.x - L1.y * H1.y;  aI11 += L1.x * H1.y + L1.y * H1.x;
        }
    }
    // epilogue: square, scatter via invmap, batch-sum
    float local = 0.f;
    int off2 = c_OFF2[j];
    float pr[4] = { aR00 * aR00 + aI00 * aI00, aR01 * aR01 + aI01 * aI01,
                    aR10 * aR10 + aI10 * aI10, aR11 * aR11 + aI11 * aI11 };
    int aa[2] = { a0 + ty, a0 + ty + 16 };
    int bb[2] = { b0 + tx, b0 + tx + 16 };
#pragma unroll
    for (int i = 0; i < 2; i++)
#pragma unroll
        for (int i2 = 0; i2 < 2; i2++) {
            if (aa[i] < n && bb[i2] < n) {
                float p = pr[i * 2 + i2];
                g_praw[b][g_invmap[off2 + aa[i] * n + bb[i2]]] = p;
                local += p;
            }
        }
    for (int off = 16; off; off >>= 1)
        local += __shfl_down_sync(0xffffffffu, local, off);
    if ((t & 31) == 0) red[t >> 5] = local;
    __syncthreads();
    if (t == 0) {
        float v = 0.f;
#pragma unroll
        for (int q = 0; q < 8; q++) v += red[q];
        atomicAdd(&g_sum[b], v);
    }
}

// ============ kernel 3: acc += praw @ weight ============
#define KCH 128
__global__ __launch_bounds__(256) void k_gemm(const float* __restrict__ weight) {
    __shared__ float pr[BATCH][KCH];
    __shared__ float red[BATCH][OUTD];
    int t = threadIdx.x;
    int n = t & 127;
    int kp = t >> 7;                      // 0..1
    int k0 = blockIdx.x * KCH;
    int klen = NST - k0; if (klen > KCH) klen = KCH;

    for (int idx = t; idx < BATCH * KCH; idx += 256) {
        int bb = idx >> 7, kk = idx & 127;
        pr[bb][kk] = (kk < klen) ? g_praw[bb][k0 + kk] : 0.f;
    }
    __syncthreads();
    float acc[BATCH];
#pragma unroll
    for (int bb = 0; bb < BATCH; bb++) acc[bb] = 0.f;
    for (int kk = kp; kk < klen; kk += 2) {
        float wv = weight[(size_t)(k0 + kk) * OUTD + n];
#pragma unroll
        for (int bb = 0; bb < BATCH; bb++) acc[bb] += wv * pr[bb][kk];
    }
    if (kp == 1) {
#pragma unroll
        for (int bb = 0; bb < BATCH; bb++) red[bb][n] = acc[bb];
    }
    __syncthreads();
    if (kp == 0) {
#pragma unroll
        for (int bb = 0; bb < BATCH; bb++)
            atomicAdd(&g_acc[bb * OUTD + n], acc[bb] + red[bb][n]);
    }
}

// ============ kernel 4: normalize + bias ============
__global__ void k_final(const float* __restrict__ bias, float* __restrict__ out) {
    int t = blockIdx.x * 256 + threadIdx.x;
    if (t < BATCH * OUTD) {
        int b = t >> 7, n = t & 127;
        out[t] = g_acc[t] / g_sum[b] + bias[n];
    }
}

// ============ launch ============
extern "C" void kernel_launch(void* const* d_in, const int* in_sizes, int n_in,
                              void* d_out, int out_size) {
    const float* x   = (const float*)d_in[0];
    const float* th1 = (const float*)d_in[1];
    const float* th2 = (const float*)d_in[2];
    const float* mr  = (const float*)d_in[3];
    const float* mi  = (const float*)d_in[4];
    const float* w   = (const float*)d_in[5];
    const float* bia = (const float*)d_in[6];
    const int* rows  = (const int*)d_in[7];
    float* out = (float*)d_out;

    k_tables<<<dim3(NDEL / CS2, 2, BATCH), 256>>>(x, th1, th2, mr, mi, rows);
    k_classes<<<dim3(NTILE, BATCH), 256>>>();
    k_gemm<<<(NST + KCH - 1) / KCH, 256>>>(w);
    k_final<<<4, 256>>>(bia, out);
}